// round 1
// baseline (speedup 1.0000x reference)
#include <cuda_runtime.h>
#include <math.h>

// Problem constants (shapes fixed by dataset; grids derived from in_sizes at launch)
#define NMAX 65536
#define HD   128

// Scratch (device globals: no allocation allowed in kernel_launch)
__device__ float g_agg1[NMAX * 32];
__device__ float g_h   [NMAX * HD];
__device__ float g_agg2[NMAX * HD];   // reused as nh2 buffer at the end
__device__ float g_h2  [NMAX * HD];
__device__ float g_t1  [NMAX * HD];
__device__ float g_pooled[64 * HD];

__device__ __forceinline__ float leakyf(float v) { return v > 0.f ? v : 0.01f * v; }

// ---------------------------------------------------------------------------
// Edge layer 1: msg = relu(x[src] + edge_attr @ e1_w + e1_b); red-add into agg1
// 8 threads per edge, each handles 4 of the 32 output channels (float4).
// ---------------------------------------------------------------------------
__global__ void edge1_kernel(const float* __restrict__ x, const int* __restrict__ src,
                             const int* __restrict__ dst, const float* __restrict__ ea,
                             const float* __restrict__ W, const float* __restrict__ bias,
                             float* __restrict__ agg, int E)
{
    __shared__ float4 sW[16 * 8];  // e1_w [16][32] as float4 [16][8]
    __shared__ float4 sB[8];
    int tid = threadIdx.x;
    if (tid < 128) sW[tid] = ((const float4*)W)[tid];
    if (tid < 8)   sB[tid] = ((const float4*)bias)[tid];
    __syncthreads();

    int e = blockIdx.x * 32 + (tid >> 3);
    if (e >= E) return;
    int sub = tid & 7;

    const float4* ea4 = (const float4*)(ea + (size_t)e * 16);
    float4 a0 = ea4[0], a1 = ea4[1], a2 = ea4[2], a3 = ea4[3];
    float av[16];
    av[0]=a0.x; av[1]=a0.y; av[2]=a0.z; av[3]=a0.w;
    av[4]=a1.x; av[5]=a1.y; av[6]=a1.z; av[7]=a1.w;
    av[8]=a2.x; av[9]=a2.y; av[10]=a2.z; av[11]=a2.w;
    av[12]=a3.x; av[13]=a3.y; av[14]=a3.z; av[15]=a3.w;

    float4 acc = sB[sub];
    #pragma unroll
    for (int k = 0; k < 16; k++) {
        float4 w = sW[k * 8 + sub];
        acc.x += av[k] * w.x; acc.y += av[k] * w.y;
        acc.z += av[k] * w.z; acc.w += av[k] * w.w;
    }

    int s = src[e], d = dst[e];
    float4 xv = *(const float4*)(x + (size_t)s * 32 + sub * 4);
    float4 m;
    m.x = fmaxf(acc.x + xv.x, 0.f);
    m.y = fmaxf(acc.y + xv.y, 0.f);
    m.z = fmaxf(acc.z + xv.z, 0.f);
    m.w = fmaxf(acc.w + xv.w, 0.f);

    float* p = agg + (size_t)d * 32 + sub * 4;
    asm volatile("red.global.add.v4.f32 [%0], {%1,%2,%3,%4};"
                 :: "l"(p), "f"(m.x), "f"(m.y), "f"(m.z), "f"(m.w) : "memory");
}

// ---------------------------------------------------------------------------
// Edge layer 2: msg = relu(h[src] + edge_attr @ e2_w + e2_b); red-add into agg2
// One warp per edge; each lane handles 4 of 128 channels.
// ---------------------------------------------------------------------------
__global__ void edge2_kernel(const float* __restrict__ h, const int* __restrict__ src,
                             const int* __restrict__ dst, const float* __restrict__ ea,
                             const float* __restrict__ W, const float* __restrict__ bias,
                             float* __restrict__ agg, int E)
{
    __shared__ float4 sW[16 * 32];  // e2_w [16][128] as float4 [16][32] = 8KB
    __shared__ float4 sB[32];
    int tid = threadIdx.x;
    for (int i = tid; i < 16 * 32; i += 256) sW[i] = ((const float4*)W)[i];
    if (tid < 32) sB[tid] = ((const float4*)bias)[tid];
    __syncthreads();

    int e = blockIdx.x * 8 + (tid >> 5);
    if (e >= E) return;
    int lane = tid & 31;

    float av = (lane < 16) ? ea[(size_t)e * 16 + lane] : 0.f;
    float4 acc = sB[lane];
    #pragma unroll
    for (int k = 0; k < 16; k++) {
        float a = __shfl_sync(0xffffffffu, av, k);
        float4 w = sW[k * 32 + lane];
        acc.x += a * w.x; acc.y += a * w.y;
        acc.z += a * w.z; acc.w += a * w.w;
    }

    int s = src[e], d = dst[e];
    float4 g = *(const float4*)(h + (size_t)s * HD + lane * 4);
    float4 m;
    m.x = fmaxf(acc.x + g.x, 0.f);
    m.y = fmaxf(acc.y + g.y, 0.f);
    m.z = fmaxf(acc.z + g.z, 0.f);
    m.w = fmaxf(acc.w + g.w, 0.f);

    float* p = agg + (size_t)d * HD + lane * 4;
    asm volatile("red.global.add.v4.f32 [%0], {%1,%2,%3,%4};"
                 :: "l"(p), "f"(m.x), "f"(m.y), "f"(m.z), "f"(m.w) : "memory");
}

// ---------------------------------------------------------------------------
// GEMM: Out[N,128] = act( (In (+In2)) @ W[K,128] + bias )
// 256 threads/block, 64 rows x 128 cols tile, per-thread 8 rows x 4 cols.
// W streamed through smem in 16-row chunks (keeps static smem <= 40KB).
// ACT: 0 = leaky_relu(0.01), 1 = relu
// ---------------------------------------------------------------------------
template<int K, int ACT, bool ADD>
__global__ void gemm_kernel(const float* __restrict__ In, const float* __restrict__ In2,
                            const float* __restrict__ W, const float* __restrict__ bias,
                            float* __restrict__ Out)
{
    __shared__ float sIn[64 * K];     // 32KB @ K=128
    __shared__ float sW[16 * 128];    // 8KB chunk
    int tid = threadIdx.x;
    int row0 = blockIdx.x * 64;

    const float4* inp  = (const float4*)(In  + (size_t)row0 * K);
    const float4* inp2 = (const float4*)(In2 + (size_t)row0 * K);
    for (int i = tid; i < (64 * K) / 4; i += 256) {
        float4 v = inp[i];
        if (ADD) {
            float4 u = inp2[i];
            v.x += u.x; v.y += u.y; v.z += u.z; v.w += u.w;
        }
        ((float4*)sIn)[i] = v;
    }

    int cx = tid & 31;    // col group (4 cols)
    int ry = tid >> 5;    // row group (8 rows)
    float4 b4 = ((const float4*)bias)[cx];
    float4 acc[8];
    #pragma unroll
    for (int m = 0; m < 8; m++) acc[m] = b4;

    for (int kc = 0; kc < K; kc += 16) {
        __syncthreads();
        for (int i = tid; i < (16 * 128) / 4; i += 256)
            ((float4*)sW)[i] = ((const float4*)(W + (size_t)kc * 128))[i];
        __syncthreads();
        #pragma unroll
        for (int k = 0; k < 16; k++) {
            float4 w = ((float4*)sW)[k * 32 + cx];
            #pragma unroll
            for (int m = 0; m < 8; m++) {
                float a = sIn[(ry * 8 + m) * K + (kc + k)];
                acc[m].x += a * w.x; acc[m].y += a * w.y;
                acc[m].z += a * w.z; acc[m].w += a * w.w;
            }
        }
    }

    #pragma unroll
    for (int m = 0; m < 8; m++) {
        float4 v = acc[m];
        if (ACT == 0) {
            v.x = leakyf(v.x); v.y = leakyf(v.y); v.z = leakyf(v.z); v.w = leakyf(v.w);
        } else {
            v.x = fmaxf(v.x, 0.f); v.y = fmaxf(v.y, 0.f);
            v.z = fmaxf(v.z, 0.f); v.w = fmaxf(v.w, 0.f);
        }
        *(float4*)(Out + (size_t)(row0 + ry * 8 + m) * 128 + cx * 4) = v;
    }
}

// ---------------------------------------------------------------------------
// Graph mean pooling: pooled[b][c] = mean_i h2[b*Nper+i][c]
// ---------------------------------------------------------------------------
__global__ void pool_kernel(const float* __restrict__ h2, float* __restrict__ pooled, int Nper)
{
    int b = blockIdx.x;
    int tid = threadIdx.x;
    int c = tid & 127, half = tid >> 7;
    float s = 0.f;
    const float* base = h2 + (size_t)b * Nper * HD + c;
    for (int i = half; i < Nper; i += 2) s += base[(size_t)i * HD];
    __shared__ float sm[256];
    sm[tid] = s;
    __syncthreads();
    if (half == 0) pooled[b * HD + c] = (sm[c] + sm[128 + c]) / (float)Nper;
}

// ---------------------------------------------------------------------------
// Action head: a = leaky(leaky(pooled@a_w1+b1)@a_w2+b2); softmax over 10.
// One block per batch element.
// ---------------------------------------------------------------------------
__global__ void action_kernel(const float* __restrict__ pooled,
                              const float* __restrict__ w1, const float* __restrict__ b1,
                              const float* __restrict__ w2, const float* __restrict__ b2,
                              float* __restrict__ out)
{
    __shared__ float sp[128], s1[128], s2[10];
    int b = blockIdx.x;
    int tid = threadIdx.x;
    sp[tid] = pooled[b * 128 + tid];
    __syncthreads();
    float acc = b1[tid];
    #pragma unroll 8
    for (int k = 0; k < 128; k++) acc += sp[k] * w1[k * 128 + tid];
    s1[tid] = leakyf(acc);
    __syncthreads();
    if (tid < 10) {
        float a2 = b2[tid];
        #pragma unroll 8
        for (int k = 0; k < 128; k++) a2 += s1[k] * w2[k * 10 + tid];
        s2[tid] = leakyf(a2);
    }
    __syncthreads();
    if (tid == 0) {
        float mx = -1e30f;
        for (int j = 0; j < 10; j++) mx = fmaxf(mx, s2[j]);
        float ex[10], sum = 0.f;
        for (int j = 0; j < 10; j++) { ex[j] = expf(s2[j] - mx); sum += ex[j]; }
        float inv = 1.f / sum;
        for (int j = 0; j < 10; j++) out[b * 10 + j] = ex[j] * inv;
    }
}

// ---------------------------------------------------------------------------
// Node score: out[(r%64)*Nper + r/64] = sigmoid(nh2[r] . n_w3 + b3); warp/row.
// ---------------------------------------------------------------------------
__global__ void score_kernel(const float* __restrict__ nh, const float* __restrict__ w3,
                             const float* __restrict__ b3, float* __restrict__ out,
                             int N, int Nper)
{
    int r = blockIdx.x * 8 + (threadIdx.x >> 5);
    int lane = threadIdx.x & 31;
    if (r >= N) return;
    float4 v = *(const float4*)(nh + (size_t)r * HD + lane * 4);
    float4 w = *(const float4*)(w3 + lane * 4);
    float acc = v.x * w.x + v.y * w.y + v.z * w.z + v.w * w.w;
    #pragma unroll
    for (int o = 16; o; o >>= 1) acc += __shfl_xor_sync(0xffffffffu, acc, o);
    if (lane == 0) {
        float z = acc + b3[0];
        out[(size_t)(r & 63) * Nper + (r >> 6)] = 1.f / (1.f + expf(-z));
    }
}

// ---------------------------------------------------------------------------
extern "C" void kernel_launch(void* const* d_in, const int* in_sizes, int n_in,
                              void* d_out, int out_size)
{
    const float* x     = (const float*)d_in[0];
    const int*   ei    = (const int*)  d_in[1];
    const float* ea    = (const float*)d_in[2];
    const float* e1_w  = (const float*)d_in[3];
    const float* e1_b  = (const float*)d_in[4];
    const float* c1_w1 = (const float*)d_in[5];
    const float* c1_b1 = (const float*)d_in[6];
    const float* c1_w2 = (const float*)d_in[7];
    const float* c1_b2 = (const float*)d_in[8];
    const float* e2_w  = (const float*)d_in[9];
    const float* e2_b  = (const float*)d_in[10];
    const float* c2_w1 = (const float*)d_in[11];
    const float* c2_b1 = (const float*)d_in[12];
    const float* c2_w2 = (const float*)d_in[13];
    const float* c2_b2 = (const float*)d_in[14];
    const float* a_w1  = (const float*)d_in[15];
    const float* a_b1  = (const float*)d_in[16];
    const float* a_w2  = (const float*)d_in[17];
    const float* a_b2  = (const float*)d_in[18];
    const float* n_w1  = (const float*)d_in[19];
    const float* n_b1  = (const float*)d_in[20];
    const float* n_w2  = (const float*)d_in[21];
    const float* n_b2  = (const float*)d_in[22];
    const float* n_w3  = (const float*)d_in[23];
    const float* n_b3  = (const float*)d_in[24];

    int N = in_sizes[0] / 32;
    int E = in_sizes[1] / 2;
    int Nper = N / 64;
    const int* src = ei;
    const int* dst = ei + E;

    float *agg1, *h, *agg2, *h2, *t1, *pooled;
    cudaGetSymbolAddress((void**)&agg1,   g_agg1);
    cudaGetSymbolAddress((void**)&h,      g_h);
    cudaGetSymbolAddress((void**)&agg2,   g_agg2);
    cudaGetSymbolAddress((void**)&h2,     g_h2);
    cudaGetSymbolAddress((void**)&t1,     g_t1);
    cudaGetSymbolAddress((void**)&pooled, g_pooled);

    float* out = (float*)d_out;

    cudaMemsetAsync(agg1, 0, (size_t)N * 32 * sizeof(float));
    cudaMemsetAsync(agg2, 0, (size_t)N * HD * sizeof(float));

    // GINE layer 1
    edge1_kernel<<<(E + 31) / 32, 256>>>(x, src, dst, ea, e1_w, e1_b, agg1, E);
    gemm_kernel<32, 0, true ><<<N / 64, 256>>>(x,  agg1, c1_w1, c1_b1, t1);
    gemm_kernel<128, 1, false><<<N / 64, 256>>>(t1, t1,   c1_w2, c1_b2, h);   // relu(leaky(z)) == relu(z)

    // GINE layer 2
    edge2_kernel<<<(E + 7) / 8, 256>>>(h, src, dst, ea, e2_w, e2_b, agg2, E);
    gemm_kernel<128, 0, true ><<<N / 64, 256>>>(h,  agg2, c2_w1, c2_b1, t1);
    gemm_kernel<128, 0, false><<<N / 64, 256>>>(t1, t1,   c2_w2, c2_b2, h2);

    // Action head
    pool_kernel<<<64, 256>>>(h2, pooled, Nper);
    action_kernel<<<64, 128>>>(pooled, a_w1, a_b1, a_w2, a_b2, out);

    // Node score head (reuse agg2 as nh2 buffer)
    gemm_kernel<128, 0, false><<<N / 64, 256>>>(h2, h2, n_w1, n_b1, t1);
    gemm_kernel<128, 0, false><<<N / 64, 256>>>(t1, t1, n_w2, n_b2, agg2);
    score_kernel<<<(N + 7) / 8, 256>>>(agg2, n_w3, n_b3, out + 640, N, Nper);
}

// round 2
// speedup vs baseline: 1.0015x; 1.0015x over previous
#include <cuda_runtime.h>
#include <math.h>

// Problem constants (shapes fixed by dataset; grids derived from in_sizes at launch)
#define NMAX 65536
#define HD   128

// Scratch (device globals: no allocation allowed in kernel_launch)
__device__ float g_agg1[NMAX * 32];
__device__ float g_h   [NMAX * HD];
__device__ float g_agg2[NMAX * HD];   // reused as nh2 buffer at the end
__device__ float g_h2  [NMAX * HD];
__device__ float g_t1  [NMAX * HD];
__device__ float g_pooled[64 * HD];

__device__ __forceinline__ float leakyf(float v) { return v > 0.f ? v : 0.01f * v; }

// ---------------------------------------------------------------------------
// Edge layer 1: msg = relu(x[src] + edge_attr @ e1_w + e1_b); red-add into agg1
// 8 threads per edge, each handles 4 of the 32 output channels (float4).
// ---------------------------------------------------------------------------
__global__ void edge1_kernel(const float* __restrict__ x, const int* __restrict__ src,
                             const int* __restrict__ dst, const float* __restrict__ ea,
                             const float* __restrict__ W, const float* __restrict__ bias,
                             float* __restrict__ agg, int E)
{
    __shared__ float4 sW[16 * 8];  // e1_w [16][32] as float4 [16][8]
    __shared__ float4 sB[8];
    int tid = threadIdx.x;
    if (tid < 128) sW[tid] = ((const float4*)W)[tid];
    if (tid < 8)   sB[tid] = ((const float4*)bias)[tid];
    __syncthreads();

    int e = blockIdx.x * 32 + (tid >> 3);
    if (e >= E) return;
    int sub = tid & 7;

    const float4* ea4 = (const float4*)(ea + (size_t)e * 16);
    float4 a0 = ea4[0], a1 = ea4[1], a2 = ea4[2], a3 = ea4[3];
    float av[16];
    av[0]=a0.x; av[1]=a0.y; av[2]=a0.z; av[3]=a0.w;
    av[4]=a1.x; av[5]=a1.y; av[6]=a1.z; av[7]=a1.w;
    av[8]=a2.x; av[9]=a2.y; av[10]=a2.z; av[11]=a2.w;
    av[12]=a3.x; av[13]=a3.y; av[14]=a3.z; av[15]=a3.w;

    float4 acc = sB[sub];
    #pragma unroll
    for (int k = 0; k < 16; k++) {
        float4 w = sW[k * 8 + sub];
        acc.x += av[k] * w.x; acc.y += av[k] * w.y;
        acc.z += av[k] * w.z; acc.w += av[k] * w.w;
    }

    int s = src[e], d = dst[e];
    float4 xv = *(const float4*)(x + (size_t)s * 32 + sub * 4);
    float4 m;
    m.x = fmaxf(acc.x + xv.x, 0.f);
    m.y = fmaxf(acc.y + xv.y, 0.f);
    m.z = fmaxf(acc.z + xv.z, 0.f);
    m.w = fmaxf(acc.w + xv.w, 0.f);

    float* p = agg + (size_t)d * 32 + sub * 4;
    asm volatile("red.global.add.v4.f32 [%0], {%1,%2,%3,%4};"
                 :: "l"(p), "f"(m.x), "f"(m.y), "f"(m.z), "f"(m.w) : "memory");
}

// ---------------------------------------------------------------------------
// Edge layer 2: msg = relu(h[src] + edge_attr @ e2_w + e2_b); red-add into agg2
// One warp per edge; each lane handles 4 of 128 channels.
// ---------------------------------------------------------------------------
__global__ void edge2_kernel(const float* __restrict__ h, const int* __restrict__ src,
                             const int* __restrict__ dst, const float* __restrict__ ea,
                             const float* __restrict__ W, const float* __restrict__ bias,
                             float* __restrict__ agg, int E)
{
    __shared__ float4 sW[16 * 32];  // e2_w [16][128] as float4 [16][32] = 8KB
    __shared__ float4 sB[32];
    int tid = threadIdx.x;
    for (int i = tid; i < 16 * 32; i += 256) sW[i] = ((const float4*)W)[i];
    if (tid < 32) sB[tid] = ((const float4*)bias)[tid];
    __syncthreads();

    int e = blockIdx.x * 8 + (tid >> 5);
    if (e >= E) return;
    int lane = tid & 31;

    float av = (lane < 16) ? ea[(size_t)e * 16 + lane] : 0.f;
    float4 acc = sB[lane];
    #pragma unroll
    for (int k = 0; k < 16; k++) {
        float a = __shfl_sync(0xffffffffu, av, k);
        float4 w = sW[k * 32 + lane];
        acc.x += a * w.x; acc.y += a * w.y;
        acc.z += a * w.z; acc.w += a * w.w;
    }

    int s = src[e], d = dst[e];
    float4 g = *(const float4*)(h + (size_t)s * HD + lane * 4);
    float4 m;
    m.x = fmaxf(acc.x + g.x, 0.f);
    m.y = fmaxf(acc.y + g.y, 0.f);
    m.z = fmaxf(acc.z + g.z, 0.f);
    m.w = fmaxf(acc.w + g.w, 0.f);

    float* p = agg + (size_t)d * HD + lane * 4;
    asm volatile("red.global.add.v4.f32 [%0], {%1,%2,%3,%4};"
                 :: "l"(p), "f"(m.x), "f"(m.y), "f"(m.z), "f"(m.w) : "memory");
}

// ---------------------------------------------------------------------------
// GEMM: Out[N,128] = act( (In (+In2)) @ W[K,128] + bias )
// 256 threads/block, 64 rows x 128 cols tile, per-thread 8 rows x 4 cols.
// W streamed through smem in 16-row chunks (keeps static smem <= 40KB).
// ACT: 0 = leaky_relu(0.01), 1 = relu
// ---------------------------------------------------------------------------
template<int K, int ACT, bool ADD>
__global__ void gemm_kernel(const float* __restrict__ In, const float* __restrict__ In2,
                            const float* __restrict__ W, const float* __restrict__ bias,
                            float* __restrict__ Out)
{
    __shared__ float sIn[64 * K];     // 32KB @ K=128
    __shared__ float sW[16 * 128];    // 8KB chunk
    int tid = threadIdx.x;
    int row0 = blockIdx.x * 64;

    const float4* inp  = (const float4*)(In  + (size_t)row0 * K);
    const float4* inp2 = (const float4*)(In2 + (size_t)row0 * K);
    for (int i = tid; i < (64 * K) / 4; i += 256) {
        float4 v = inp[i];
        if (ADD) {
            float4 u = inp2[i];
            v.x += u.x; v.y += u.y; v.z += u.z; v.w += u.w;
        }
        ((float4*)sIn)[i] = v;
    }

    int cx = tid & 31;    // col group (4 cols)
    int ry = tid >> 5;    // row group (8 rows)
    float4 b4 = ((const float4*)bias)[cx];
    float4 acc[8];
    #pragma unroll
    for (int m = 0; m < 8; m++) acc[m] = b4;

    for (int kc = 0; kc < K; kc += 16) {
        __syncthreads();
        for (int i = tid; i < (16 * 128) / 4; i += 256)
            ((float4*)sW)[i] = ((const float4*)(W + (size_t)kc * 128))[i];
        __syncthreads();
        #pragma unroll
        for (int k = 0; k < 16; k++) {
            float4 w = ((float4*)sW)[k * 32 + cx];
            #pragma unroll
            for (int m = 0; m < 8; m++) {
                float a = sIn[(ry * 8 + m) * K + (kc + k)];
                acc[m].x += a * w.x; acc[m].y += a * w.y;
                acc[m].z += a * w.z; acc[m].w += a * w.w;
            }
        }
    }

    #pragma unroll
    for (int m = 0; m < 8; m++) {
        float4 v = acc[m];
        if (ACT == 0) {
            v.x = leakyf(v.x); v.y = leakyf(v.y); v.z = leakyf(v.z); v.w = leakyf(v.w);
        } else {
            v.x = fmaxf(v.x, 0.f); v.y = fmaxf(v.y, 0.f);
            v.z = fmaxf(v.z, 0.f); v.w = fmaxf(v.w, 0.f);
        }
        *(float4*)(Out + (size_t)(row0 + ry * 8 + m) * 128 + cx * 4) = v;
    }
}

// ---------------------------------------------------------------------------
// Graph mean pooling: pooled[b][c] = mean_i h2[b*Nper+i][c]
// ---------------------------------------------------------------------------
__global__ void pool_kernel(const float* __restrict__ h2, float* __restrict__ pooled, int Nper)
{
    int b = blockIdx.x;
    int tid = threadIdx.x;
    int c = tid & 127, half = tid >> 7;
    float s = 0.f;
    const float* base = h2 + (size_t)b * Nper * HD + c;
    for (int i = half; i < Nper; i += 2) s += base[(size_t)i * HD];
    __shared__ float sm[256];
    sm[tid] = s;
    __syncthreads();
    if (half == 0) pooled[b * HD + c] = (sm[c] + sm[128 + c]) / (float)Nper;
}

// ---------------------------------------------------------------------------
// Action head: a = leaky(leaky(pooled@a_w1+b1)@a_w2+b2); softmax over 10.
// One block per batch element.
// ---------------------------------------------------------------------------
__global__ void action_kernel(const float* __restrict__ pooled,
                              const float* __restrict__ w1, const float* __restrict__ b1,
                              const float* __restrict__ w2, const float* __restrict__ b2,
                              float* __restrict__ out)
{
    __shared__ float sp[128], s1[128], s2[10];
    int b = blockIdx.x;
    int tid = threadIdx.x;
    sp[tid] = pooled[b * 128 + tid];
    __syncthreads();
    float acc = b1[tid];
    #pragma unroll 8
    for (int k = 0; k < 128; k++) acc += sp[k] * w1[k * 128 + tid];
    s1[tid] = leakyf(acc);
    __syncthreads();
    if (tid < 10) {
        float a2 = b2[tid];
        #pragma unroll 8
        for (int k = 0; k < 128; k++) a2 += s1[k] * w2[k * 10 + tid];
        s2[tid] = leakyf(a2);
    }
    __syncthreads();
    if (tid == 0) {
        float mx = -1e30f;
        for (int j = 0; j < 10; j++) mx = fmaxf(mx, s2[j]);
        float ex[10], sum = 0.f;
        for (int j = 0; j < 10; j++) { ex[j] = expf(s2[j] - mx); sum += ex[j]; }
        float inv = 1.f / sum;
        for (int j = 0; j < 10; j++) out[b * 10 + j] = ex[j] * inv;
    }
}

// ---------------------------------------------------------------------------
// Node score: out[(r%64)*Nper + r/64] = sigmoid(nh2[r] . n_w3 + b3); warp/row.
// ---------------------------------------------------------------------------
__global__ void score_kernel(const float* __restrict__ nh, const float* __restrict__ w3,
                             const float* __restrict__ b3, float* __restrict__ out,
                             int N, int Nper)
{
    int r = blockIdx.x * 8 + (threadIdx.x >> 5);
    int lane = threadIdx.x & 31;
    if (r >= N) return;
    float4 v = *(const float4*)(nh + (size_t)r * HD + lane * 4);
    float4 w = *(const float4*)(w3 + lane * 4);
    float acc = v.x * w.x + v.y * w.y + v.z * w.z + v.w * w.w;
    #pragma unroll
    for (int o = 16; o; o >>= 1) acc += __shfl_xor_sync(0xffffffffu, acc, o);
    if (lane == 0) {
        float z = acc + b3[0];
        out[(size_t)(r & 63) * Nper + (r >> 6)] = 1.f / (1.f + expf(-z));
    }
}

// ---------------------------------------------------------------------------
extern "C" void kernel_launch(void* const* d_in, const int* in_sizes, int n_in,
                              void* d_out, int out_size)
{
    const float* x     = (const float*)d_in[0];
    const int*   ei    = (const int*)  d_in[1];
    const float* ea    = (const float*)d_in[2];
    const float* e1_w  = (const float*)d_in[3];
    const float* e1_b  = (const float*)d_in[4];
    const float* c1_w1 = (const float*)d_in[5];
    const float* c1_b1 = (const float*)d_in[6];
    const float* c1_w2 = (const float*)d_in[7];
    const float* c1_b2 = (const float*)d_in[8];
    const float* e2_w  = (const float*)d_in[9];
    const float* e2_b  = (const float*)d_in[10];
    const float* c2_w1 = (const float*)d_in[11];
    const float* c2_b1 = (const float*)d_in[12];
    const float* c2_w2 = (const float*)d_in[13];
    const float* c2_b2 = (const float*)d_in[14];
    const float* a_w1  = (const float*)d_in[15];
    const float* a_b1  = (const float*)d_in[16];
    const float* a_w2  = (const float*)d_in[17];
    const float* a_b2  = (const float*)d_in[18];
    const float* n_w1  = (const float*)d_in[19];
    const float* n_b1  = (const float*)d_in[20];
    const float* n_w2  = (const float*)d_in[21];
    const float* n_b2  = (const float*)d_in[22];
    const float* n_w3  = (const float*)d_in[23];
    const float* n_b3  = (const float*)d_in[24];

    int N = in_sizes[0] / 32;
    int E = in_sizes[1] / 2;
    int Nper = N / 64;
    const int* src = ei;
    const int* dst = ei + E;

    float *agg1, *h, *agg2, *h2, *t1, *pooled;
    cudaGetSymbolAddress((void**)&agg1,   g_agg1);
    cudaGetSymbolAddress((void**)&h,      g_h);
    cudaGetSymbolAddress((void**)&agg2,   g_agg2);
    cudaGetSymbolAddress((void**)&h2,     g_h2);
    cudaGetSymbolAddress((void**)&t1,     g_t1);
    cudaGetSymbolAddress((void**)&pooled, g_pooled);

    float* out = (float*)d_out;

    cudaMemsetAsync(agg1, 0, (size_t)N * 32 * sizeof(float));
    cudaMemsetAsync(agg2, 0, (size_t)N * HD * sizeof(float));

    // GINE layer 1
    edge1_kernel<<<(E + 31) / 32, 256>>>(x, src, dst, ea, e1_w, e1_b, agg1, E);
    gemm_kernel<32, 0, true ><<<N / 64, 256>>>(x,  agg1, c1_w1, c1_b1, t1);
    gemm_kernel<128, 1, false><<<N / 64, 256>>>(t1, t1,   c1_w2, c1_b2, h);   // relu(leaky(z)) == relu(z)

    // GINE layer 2
    edge2_kernel<<<(E + 7) / 8, 256>>>(h, src, dst, ea, e2_w, e2_b, agg2, E);
    gemm_kernel<128, 0, true ><<<N / 64, 256>>>(h,  agg2, c2_w1, c2_b1, t1);
    gemm_kernel<128, 0, false><<<N / 64, 256>>>(t1, t1,   c2_w2, c2_b2, h2);

    // Action head
    pool_kernel<<<64, 256>>>(h2, pooled, Nper);
    action_kernel<<<64, 128>>>(pooled, a_w1, a_b1, a_w2, a_b2, out);

    // Node score head (reuse agg2 as nh2 buffer)
    gemm_kernel<128, 0, false><<<N / 64, 256>>>(h2, h2, n_w1, n_b1, t1);
    gemm_kernel<128, 0, false><<<N / 64, 256>>>(t1, t1, n_w2, n_b2, agg2);
    score_kernel<<<(N + 7) / 8, 256>>>(agg2, n_w3, n_b3, out + 640, N, Nper);
}